// round 4
// baseline (speedup 1.0000x reference)
#include <cuda_runtime.h>
#include <cuda_bf16.h>
#include <cstdint>

#define DEVINL __device__ __forceinline__

// ---------------- problem constants ----------------
constexpr int F  = 128;      // feature dim (K)
constexpr int B  = 256;      // batch
constexpr int R  = 512;      // J*B GEMM rows
constexpr int Q  = 65536;    // queue size
constexpr int TN = 64;       // queue rows per chunk
constexpr int QG = Q / TN;   // 1024 chunks per row-half
constexpr int SLOTS = 148;   // persistent CTA slots per row-half (1/SM per cg)
constexpr int SSTR = 272;    // padded bf16 row stride in smem bytes (256 data + 16 pad)
constexpr float INV_T = 10.0f;
constexpr float LOG2E = 1.4426950408889634f;
constexpr float CEXP  = INV_T * LOG2E;   // exp(10*d) = 2^(CEXP*d)

constexpr int BUF_BYTES  = TN * SSTR;        // 17408
constexpr int SMEM_BYTES = 2 * BUF_BYTES;    // 34816 (double buffer)

// ---------------- scratch (no allocs allowed) ----------------
__device__ alignas(16) __nv_bfloat16 g_qbf[Q * F];   // queue in bf16 (16 MB)
__device__ alignas(16) __nv_bfloat16 g_vbf[R * F];   // V in bf16
__device__ float g_sq[SLOTS * R];                    // per-slot row partials

// ---------------- helpers ----------------
DEVINL float ex2f(float x) { float y; asm("ex2.approx.ftz.f32 %0, %1;" : "=f"(y) : "f"(x)); return y; }

DEVINL uint32_t cvt2(float a, float b) {
    __nv_bfloat162 h = __floats2bfloat162_rn(a, b);
    return *reinterpret_cast<uint32_t*>(&h);
}

DEVINL uint32_t smem_u32(const void* p) {
    uint32_t a;
    asm("{ .reg .u64 t; cvta.to.shared.u64 t, %1; cvt.u32.u64 %0, t; }" : "=r"(a) : "l"(p));
    return a;
}

// mma.sync m16n8k16 row.col bf16 -> f32 accumulate
DEVINL void mma16816(float* d, const uint32_t* a, uint32_t b0, uint32_t b1) {
    asm volatile(
        "mma.sync.aligned.m16n8k16.row.col.f32.bf16.bf16.f32 "
        "{%0,%1,%2,%3}, {%4,%5,%6,%7}, {%8,%9}, {%0,%1,%2,%3};"
        : "+f"(d[0]), "+f"(d[1]), "+f"(d[2]), "+f"(d[3])
        : "r"(a[0]), "r"(a[1]), "r"(a[2]), "r"(a[3]), "r"(b0), "r"(b1));
}

DEVINL void ldsm_x4(uint32_t* r, uint32_t addr) {
    asm volatile("ldmatrix.sync.aligned.m8n8.x4.shared.b16 {%0,%1,%2,%3}, [%4];"
                 : "=r"(r[0]), "=r"(r[1]), "=r"(r[2]), "=r"(r[3]) : "r"(addr));
}

DEVINL void cp16(uint32_t smem_dst, const void* gsrc) {
    asm volatile("cp.async.cg.shared.global [%0], [%1], 16;" :: "r"(smem_dst), "l"(gsrc));
}
DEVINL void cp_commit() { asm volatile("cp.async.commit_group;" ::: "memory"); }
DEVINL void cp_wait1()  { asm volatile("cp.async.wait_group 1;" ::: "memory"); }

// ================= kernel 1: fp32 -> bf16 conversion (queue + V) =================
__global__ void cvt_kernel(const float* __restrict__ V, const float* __restrict__ queue) {
    const int QF4 = Q * F / 4;           // float4 count for queue
    const int VF4 = R * F / 4;
    int stride = gridDim.x * blockDim.x;
    for (int i = blockIdx.x * blockDim.x + threadIdx.x; i < QF4 + VF4; i += stride) {
        if (i < QF4) {
            float4 v = ((const float4*)queue)[i];
            uint2 o; o.x = cvt2(v.x, v.y); o.y = cvt2(v.z, v.w);
            ((uint2*)g_qbf)[i] = o;
        } else {
            int j = i - QF4;
            float4 v = ((const float4*)V)[j];
            uint2 o; o.x = cvt2(v.x, v.y); o.y = cvt2(v.z, v.w);
            ((uint2*)g_vbf)[j] = o;
        }
    }
}

// ================= kernel 2: persistent HMMA GEMM + fused exp row-sum =================
// grid = (2, SLOTS). CTA (cg, slot): rows [cg*256, +256), chunks qg = slot, slot+148, ...
__global__ void __launch_bounds__(256, 2)
gemm_exp_kernel() {
    __shared__ alignas(16) char smem[SMEM_BYTES];
    const uint32_t sb = smem_u32(smem);

    const int tid  = threadIdx.x;
    const int w    = tid >> 5;
    const int lane = tid & 31;
    const int g    = lane >> 2;      // 0..7
    const int tg   = lane & 3;       // 0..3
    const int cg   = blockIdx.x;     // 0..1
    const int slot = blockIdx.y;     // 0..147

    // ---- A fragments (bf16, register-resident for whole kernel) ----
    uint32_t a[2][8][4];
    {
        const uint32_t* Ab = (const uint32_t*)g_vbf + (size_t)(cg * 256 + w * 32) * (F / 2);
#pragma unroll
        for (int m = 0; m < 2; m++)
#pragma unroll
            for (int k = 0; k < 8; k++) {
                int r0 = (m * 16 + g) * (F / 2), r1 = r0 + 8 * (F / 2);
                a[m][k][0] = Ab[r0 + k * 8 + tg];
                a[m][k][1] = Ab[r1 + k * 8 + tg];
                a[m][k][2] = Ab[r0 + k * 8 + tg + 4];
                a[m][k][3] = Ab[r1 + k * 8 + tg + 4];
            }
    }

    // staging: 64 rows x 256B per chunk; each thread copies 4x16B
    const int srow = tid >> 2;            // 0..63
    const int sseg = (tid & 3) * 4;       // 0,4,8,12 (16B segments)
    auto stage = [&](int buf, int qg) {
        const char* src = (const char*)g_qbf + ((size_t)qg * TN + srow) * (F * 2) + sseg * 16;
        uint32_t dst = sb + buf * BUF_BYTES + srow * SSTR + sseg * 16;
#pragma unroll
        for (int j = 0; j < 4; j++) cp16(dst + j * 16, src + j * 16);
    };

    const int nch = (QG - slot + SLOTS - 1) / SLOTS;   // 6 or 7 chunks

    float s[2][2] = {{0.f, 0.f}, {0.f, 0.f}};

    stage(0, slot);
    cp_commit();

    int qg = slot;
#pragma unroll 1
    for (int c = 0; c < nch; c++, qg += SLOTS) {
        if (c + 1 < nch) stage((c + 1) & 1, qg + SLOTS);
        cp_commit();
        cp_wait1();
        __syncthreads();

        const uint32_t bbase = sb + (c & 1) * BUF_BYTES;
        // lane-addressed base for ldmatrix.x4: rows l&7, tile (l>>3) at +16B each
        const uint32_t lbase = bbase + (lane & 7) * SSTR + (lane >> 3) * 16;

#pragma unroll
        for (int n8 = 0; n8 < TN / 8; n8++) {
            uint32_t b[16];
            const uint32_t nb = lbase + n8 * 8 * SSTR;
#pragma unroll
            for (int kp = 0; kp < 4; kp++) ldsm_x4(b + kp * 4, nb + kp * 64);

            float acc0[4] = {0.f, 0.f, 0.f, 0.f};
            float acc1[4] = {0.f, 0.f, 0.f, 0.f};
#pragma unroll
            for (int k = 0; k < 8; k++) {
                uint32_t b0 = b[(k >> 1) * 4 + (k & 1) * 2];
                uint32_t b1 = b[(k >> 1) * 4 + (k & 1) * 2 + 1];
                mma16816(acc0, a[0][k], b0, b1);
                mma16816(acc1, a[1][k], b0, b1);
            }
            s[0][0] += ex2f(acc0[0] * CEXP) + ex2f(acc0[1] * CEXP);
            s[0][1] += ex2f(acc0[2] * CEXP) + ex2f(acc0[3] * CEXP);
            s[1][0] += ex2f(acc1[0] * CEXP) + ex2f(acc1[1] * CEXP);
            s[1][1] += ex2f(acc1[2] * CEXP) + ex2f(acc1[3] * CEXP);
        }
        __syncthreads();
    }

    // ---- quad reduce over tg (n sub-columns), deterministic store ----
#pragma unroll
    for (int m = 0; m < 2; m++)
#pragma unroll
        for (int i = 0; i < 2; i++) {
            s[m][i] += __shfl_xor_sync(0xFFFFFFFFu, s[m][i], 1);
            s[m][i] += __shfl_xor_sync(0xFFFFFFFFu, s[m][i], 2);
        }
    if (tg == 0) {
        float* dst = g_sq + (size_t)slot * R + cg * 256 + w * 32;
        dst[g]      = s[0][0];
        dst[g + 8]  = s[0][1];
        dst[g + 16] = s[1][0];
        dst[g + 24] = s[1][1];
    }
}

// ================= kernel 3: pos + reduce + loss =================
__global__ void finalize_kernel(const float* __restrict__ V, const float* __restrict__ L,
                                float* __restrict__ out) {
    __shared__ float sh[R];
    int t = threadIdx.x;          // 512 threads
    // pos[t] in exact fp32
    float pos;
    {
        const float4* v = (const float4*)(V + (size_t)t * F);
        const float4* l = (const float4*)(L + (size_t)(t & (B - 1)) * F);
        float acc = 0.f;
#pragma unroll
        for (int i = 0; i < F / 4; i++) {
            float4 a = v[i], c = l[i];
            acc += a.x * c.x + a.y * c.y + a.z * c.z + a.w * c.w;
        }
        pos = acc * INV_T;
    }
    sh[t] = ex2f(pos * LOG2E);    // exp(pos)
    __syncthreads();
    // per-j sums (two independent 256-halves)
    for (int off = 128; off > 0; off >>= 1) {
        if ((t & 255) < off) sh[t] += sh[t + off];
        __syncthreads();
    }
    float spos = sh[(t >> 8) << 8];
    __syncthreads();
    // reduce S_q over SLOTS partials (coalesced, deterministic)
    float sq = 0.f;
#pragma unroll 4
    for (int i = 0; i < SLOTS; i++) sq += g_sq[(size_t)i * R + t];
    sh[t] = pos - logf(spos + sq);
    __syncthreads();
    for (int off = 256; off > 0; off >>= 1) {
        if (t < off) sh[t] += sh[t + off];
        __syncthreads();
    }
    if (t == 0) out[0] = -sh[0] / (float)B;
}

// ================= launch =================
extern "C" void kernel_launch(void* const* d_in, const int* in_sizes, int n_in,
                              void* d_out, int out_size) {
    (void)in_sizes; (void)n_in; (void)out_size;
    const float* V     = (const float*)d_in[0];
    const float* L     = (const float*)d_in[1];
    const float* queue = (const float*)d_in[2];
    float* out = (float*)d_out;

    cvt_kernel<<<512, 256>>>(V, queue);
    gemm_exp_kernel<<<dim3(2, SLOTS), 256>>>();
    finalize_kernel<<<1, 512>>>(V, L, out);
}

// round 5
// speedup vs baseline: 1.0781x; 1.0781x over previous
#include <cuda_runtime.h>
#include <cuda_bf16.h>
#include <cstdint>

#define DEVINL __device__ __forceinline__

// ---------------- problem constants ----------------
constexpr int F  = 128;      // feature dim (K)
constexpr int B  = 256;      // batch
constexpr int R  = 512;      // J*B GEMM rows
constexpr int Q  = 65536;    // queue size
constexpr int TN = 64;       // queue rows per chunk
constexpr int QG = Q / TN;   // 1024 chunks
constexpr int SLOTS = 148;   // persistent CTAs (1 per SM)
constexpr int SSTR = 272;    // padded bf16 row stride in smem bytes (256 data + 16 pad)
constexpr float INV_T = 10.0f;
constexpr float LOG2E = 1.4426950408889634f;
constexpr float CEXP  = INV_T * LOG2E;   // exp(10*d) = 2^(CEXP*d)

constexpr int F32_BUF  = TN * F * 4;     // 32768 raw fp32 chunk
constexpr int BF_BUF   = TN * SSTR;      // 17408 padded bf16 tile
// smem: [2 x fp32 stage][2 x bf16 tile]
constexpr int SMEM_BYTES = 2 * F32_BUF + 2 * BF_BUF;   // 100352

// ---------------- scratch (no allocs allowed) ----------------
__device__ float g_sq[SLOTS * R];        // per-slot row partials

// ---------------- helpers ----------------
DEVINL float ex2f(float x) { float y; asm("ex2.approx.ftz.f32 %0, %1;" : "=f"(y) : "f"(x)); return y; }

DEVINL uint32_t cvt2(float a, float b) {
    __nv_bfloat162 h = __floats2bfloat162_rn(a, b);
    return *reinterpret_cast<uint32_t*>(&h);
}

DEVINL uint32_t smem_u32(const void* p) {
    uint32_t a;
    asm("{ .reg .u64 t; cvta.to.shared.u64 t, %1; cvt.u32.u64 %0, t; }" : "=r"(a) : "l"(p));
    return a;
}

// mma.sync m16n8k16 row.col bf16 -> f32 accumulate
DEVINL void mma16816(float* d, const uint32_t* a, uint32_t b0, uint32_t b1) {
    asm volatile(
        "mma.sync.aligned.m16n8k16.row.col.f32.bf16.bf16.f32 "
        "{%0,%1,%2,%3}, {%4,%5,%6,%7}, {%8,%9}, {%0,%1,%2,%3};"
        : "+f"(d[0]), "+f"(d[1]), "+f"(d[2]), "+f"(d[3])
        : "r"(a[0]), "r"(a[1]), "r"(a[2]), "r"(a[3]), "r"(b0), "r"(b1));
}

DEVINL void ldsm_x4(uint32_t* r, uint32_t addr) {
    asm volatile("ldmatrix.sync.aligned.m8n8.x4.shared.b16 {%0,%1,%2,%3}, [%4];"
                 : "=r"(r[0]), "=r"(r[1]), "=r"(r[2]), "=r"(r[3]) : "r"(addr));
}

DEVINL void cp16(uint32_t smem_dst, const void* gsrc) {
    asm volatile("cp.async.cg.shared.global [%0], [%1], 16;" :: "r"(smem_dst), "l"(gsrc));
}
DEVINL void cp_commit() { asm volatile("cp.async.commit_group;" ::: "memory"); }
DEVINL void cp_wait1()  { asm volatile("cp.async.wait_group 1;" ::: "memory"); }

// ================= kernel 1: persistent HMMA GEMM, fused cvt + exp row-sum =================
// grid = SLOTS. CTA slot: all 512 rows x chunks qg = slot, slot+SLOTS, ...
__global__ void __launch_bounds__(512, 1)
gemm_exp_kernel(const float* __restrict__ V, const float* __restrict__ queue) {
    extern __shared__ char smem[];
    const uint32_t sb = smem_u32(smem);
    const uint32_t f32b = sb;                    // 2 x F32_BUF
    const uint32_t bf_b = sb + 2 * F32_BUF;      // 2 x BF_BUF

    const int tid  = threadIdx.x;                // 0..511
    const int w    = tid >> 5;                   // 0..15 -> rows w*32..+31
    const int lane = tid & 31;
    const int g    = lane >> 2;                  // 0..7
    const int tg   = lane & 3;                   // 0..3
    const int slot = blockIdx.x;                 // 0..147

    // ---- A fragments: fp32 V -> bf16 regs, resident for whole kernel ----
    uint32_t a[2][8][4];
    {
        const float* Ab = V + (size_t)(w * 32) * F;
#pragma unroll
        for (int m = 0; m < 2; m++)
#pragma unroll
            for (int k = 0; k < 8; k++) {
                int r0 = m * 16 + g, r1 = r0 + 8;
                int c0 = k * 16 + 2 * tg, c1 = c0 + 8;
                float2 f;
                f = *(const float2*)(Ab + r0 * F + c0); a[m][k][0] = cvt2(f.x, f.y);
                f = *(const float2*)(Ab + r1 * F + c0); a[m][k][1] = cvt2(f.x, f.y);
                f = *(const float2*)(Ab + r0 * F + c1); a[m][k][2] = cvt2(f.x, f.y);
                f = *(const float2*)(Ab + r1 * F + c1); a[m][k][3] = cvt2(f.x, f.y);
            }
    }

    // fp32 staging: 64 rows x 512B; each thread 4 x 16B (8 thr/row)
    const int srow = tid >> 3;               // 0..63
    const int sseg = (tid & 7) * 64;         // byte offset within row, 64B per thread
    auto stage = [&](int buf, int qg) {
        const char* src = (const char*)(queue + (size_t)qg * TN * F) + srow * 512 + sseg;
        uint32_t dst = f32b + buf * F32_BUF + srow * 512 + sseg;
#pragma unroll
        for (int j = 0; j < 4; j++) cp16(dst + j * 16, src + j * 16);
    };

    // convert: fp32 buf -> padded bf16 tile; thread handles 4 float4 (32B bf16 out)
    auto convert = [&](int buf) {
        const float4* srcr = (const float4*)(smem + buf * F32_BUF) + srow * 32 + (tid & 7) * 4;
        char* dstr = smem + 2 * F32_BUF + buf * BF_BUF + srow * SSTR + (tid & 7) * 32;
#pragma unroll
        for (int j = 0; j < 4; j++) {
            float4 v4 = srcr[j];
            uint2 o; o.x = cvt2(v4.x, v4.y); o.y = cvt2(v4.z, v4.w);
            *reinterpret_cast<uint2*>(dstr + j * 8) = o;
        }
    };

    const int nch = (QG - slot + SLOTS - 1) / SLOTS;   // 6 or 7

    float s[2][2] = {{0.f, 0.f}, {0.f, 0.f}};

    stage(0, slot);
    cp_commit();

    int qg = slot;
#pragma unroll 1
    for (int c = 0; c < nch; c++, qg += SLOTS) {
        if (c + 1 < nch) stage((c + 1) & 1, qg + SLOTS);
        cp_commit();
        cp_wait1();               // fp32 buf (c&1) landed
        __syncthreads();          // all stage writes of c visible; prior mma done re: bf16 buf reuse
        convert(c & 1);
        __syncthreads();          // bf16 tile (c&1) ready for all warps

        const uint32_t bbase = bf_b + (c & 1) * BF_BUF;
        const uint32_t lbase = bbase + (lane & 7) * SSTR + (lane >> 3) * 16;

#pragma unroll
        for (int n8 = 0; n8 < TN / 8; n8++) {
            uint32_t b[16];
            const uint32_t nb = lbase + n8 * 8 * SSTR;
#pragma unroll
            for (int kp = 0; kp < 4; kp++) ldsm_x4(b + kp * 4, nb + kp * 64);

            float acc0[4] = {0.f, 0.f, 0.f, 0.f};
            float acc1[4] = {0.f, 0.f, 0.f, 0.f};
#pragma unroll
            for (int k = 0; k < 8; k++) {
                uint32_t b0 = b[(k >> 1) * 4 + (k & 1) * 2];
                uint32_t b1 = b[(k >> 1) * 4 + (k & 1) * 2 + 1];
                mma16816(acc0, a[0][k], b0, b1);
                mma16816(acc1, a[1][k], b0, b1);
            }
            s[0][0] += ex2f(acc0[0] * CEXP) + ex2f(acc0[1] * CEXP);
            s[0][1] += ex2f(acc0[2] * CEXP) + ex2f(acc0[3] * CEXP);
            s[1][0] += ex2f(acc1[0] * CEXP) + ex2f(acc1[1] * CEXP);
            s[1][1] += ex2f(acc1[2] * CEXP) + ex2f(acc1[3] * CEXP);
        }
        // no trailing sync needed: next iteration's pre-convert __syncthreads()
        // orders every warp's mma(c) before convert(c+1) touches the other buffer,
        // and before convert(c+2) can touch this one (two barriers in between).
    }

    // ---- quad reduce over tg (n sub-columns), deterministic store ----
#pragma unroll
    for (int m = 0; m < 2; m++)
#pragma unroll
        for (int i = 0; i < 2; i++) {
            s[m][i] += __shfl_xor_sync(0xFFFFFFFFu, s[m][i], 1);
            s[m][i] += __shfl_xor_sync(0xFFFFFFFFu, s[m][i], 2);
        }
    if (tg == 0) {
        float* dst = g_sq + (size_t)slot * R + w * 32;
        dst[g]      = s[0][0];
        dst[g + 8]  = s[0][1];
        dst[g + 16] = s[1][0];
        dst[g + 24] = s[1][1];
    }
}

// ================= kernel 2: pos + reduce + loss =================
__global__ void finalize_kernel(const float* __restrict__ V, const float* __restrict__ L,
                                float* __restrict__ out) {
    __shared__ float sh[R];
    int t = threadIdx.x;          // 512 threads
    float pos;
    {
        const float4* v = (const float4*)(V + (size_t)t * F);
        const float4* l = (const float4*)(L + (size_t)(t & (B - 1)) * F);
        float acc = 0.f;
#pragma unroll
        for (int i = 0; i < F / 4; i++) {
            float4 a = v[i], c = l[i];
            acc += a.x * c.x + a.y * c.y + a.z * c.z + a.w * c.w;
        }
        pos = acc * INV_T;
    }
    sh[t] = ex2f(pos * LOG2E);    // exp(pos)
    __syncthreads();
    for (int off = 128; off > 0; off >>= 1) {
        if ((t & 255) < off) sh[t] += sh[t + off];
        __syncthreads();
    }
    float spos = sh[(t >> 8) << 8];
    __syncthreads();
    float sq = 0.f;
#pragma unroll 8
    for (int i = 0; i < SLOTS; i++) sq += g_sq[(size_t)i * R + t];
    sh[t] = pos - logf(spos + sq);
    __syncthreads();
    for (int off = 256; off > 0; off >>= 1) {
        if (t < off) sh[t] += sh[t + off];
        __syncthreads();
    }
    if (t == 0) out[0] = -sh[0] / (float)B;
}

// ================= launch =================
extern "C" void kernel_launch(void* const* d_in, const int* in_sizes, int n_in,
                              void* d_out, int out_size) {
    (void)in_sizes; (void)n_in; (void)out_size;
    const float* V     = (const float*)d_in[0];
    const float* L     = (const float*)d_in[1];
    const float* queue = (const float*)d_in[2];
    float* out = (float*)d_out;

    cudaFuncSetAttribute(gemm_exp_kernel, cudaFuncAttributeMaxDynamicSharedMemorySize, SMEM_BYTES);

    gemm_exp_kernel<<<SLOTS, 512, SMEM_BYTES>>>(V, queue);
    finalize_kernel<<<1, 512>>>(V, L, out);
}

// round 6
// speedup vs baseline: 1.7395x; 1.6135x over previous
#include <cuda_runtime.h>
#include <cuda_bf16.h>
#include <cstdint>

#define DEVINL __device__ __forceinline__

// ---------------- problem constants ----------------
constexpr int F  = 128;      // feature dim (K)
constexpr int B  = 256;      // batch
constexpr int R  = 512;      // J*B GEMM rows
constexpr int Q  = 65536;    // queue size
constexpr int TN = 64;       // queue rows per chunk
constexpr int QG = Q / TN;   // 1024 chunks
constexpr int SLOTS = 148;   // persistent CTAs (1 per SM)
constexpr int SSTR = 272;    // padded bf16 row stride in smem bytes (256 data + 16 pad)
constexpr float INV_T = 10.0f;
constexpr float LOG2E = 1.4426950408889634f;
constexpr float CEXP  = INV_T * LOG2E;   // exp(10*d) = 2^(CEXP*d)

constexpr int F32_BUF  = TN * F * 4;     // 32768 raw fp32 chunk
constexpr int BF_BUF   = TN * SSTR;      // 17408 padded bf16 tile
constexpr int SMEM_BYTES = 2 * F32_BUF + 2 * BF_BUF;   // 100352

// ---------------- scratch (no allocs allowed) ----------------
__device__ float g_sq[R * SLOTS];        // [row][slot] partials (transposed!)
__device__ float g_pos[R];
__device__ float g_sqrow[R];

// ---------------- helpers ----------------
DEVINL float ex2f(float x) { float y; asm("ex2.approx.ftz.f32 %0, %1;" : "=f"(y) : "f"(x)); return y; }

DEVINL uint32_t cvt2(float a, float b) {
    __nv_bfloat162 h = __floats2bfloat162_rn(a, b);
    return *reinterpret_cast<uint32_t*>(&h);
}

DEVINL uint32_t smem_u32(const void* p) {
    uint32_t a;
    asm("{ .reg .u64 t; cvta.to.shared.u64 t, %1; cvt.u32.u64 %0, t; }" : "=r"(a) : "l"(p));
    return a;
}

DEVINL void mma16816(float* d, const uint32_t* a, uint32_t b0, uint32_t b1) {
    asm volatile(
        "mma.sync.aligned.m16n8k16.row.col.f32.bf16.bf16.f32 "
        "{%0,%1,%2,%3}, {%4,%5,%6,%7}, {%8,%9}, {%0,%1,%2,%3};"
        : "+f"(d[0]), "+f"(d[1]), "+f"(d[2]), "+f"(d[3])
        : "r"(a[0]), "r"(a[1]), "r"(a[2]), "r"(a[3]), "r"(b0), "r"(b1));
}

DEVINL void ldsm_x4(uint32_t* r, uint32_t addr) {
    asm volatile("ldmatrix.sync.aligned.m8n8.x4.shared.b16 {%0,%1,%2,%3}, [%4];"
                 : "=r"(r[0]), "=r"(r[1]), "=r"(r[2]), "=r"(r[3]) : "r"(addr));
}

DEVINL void cp16(uint32_t smem_dst, const void* gsrc) {
    asm volatile("cp.async.cg.shared.global [%0], [%1], 16;" :: "r"(smem_dst), "l"(gsrc));
}
DEVINL void cp_commit() { asm volatile("cp.async.commit_group;" ::: "memory"); }
DEVINL void cp_wait1()  { asm volatile("cp.async.wait_group 1;" ::: "memory"); }

// ================= kernel 1: persistent HMMA GEMM, fused cvt + exp row-sum =================
__global__ void __launch_bounds__(512, 1)
gemm_exp_kernel(const float* __restrict__ V, const float* __restrict__ queue) {
    extern __shared__ char smem[];
    const uint32_t sb   = smem_u32(smem);
    const uint32_t bf_b = sb + 2 * F32_BUF;

    const int tid  = threadIdx.x;                // 0..511
    const int w    = tid >> 5;                   // 0..15 -> rows w*32..+31
    const int lane = tid & 31;
    const int g    = lane >> 2;
    const int tg   = lane & 3;
    const int slot = blockIdx.x;                 // 0..147

    // ---- A fragments: fp32 V -> bf16 regs, PRE-SCALED by CEXP ----
    uint32_t a[2][8][4];
    {
        const float* Ab = V + (size_t)(w * 32) * F;
#pragma unroll
        for (int m = 0; m < 2; m++)
#pragma unroll
            for (int k = 0; k < 8; k++) {
                int r0 = m * 16 + g, r1 = r0 + 8;
                int c0 = k * 16 + 2 * tg, c1 = c0 + 8;
                float2 f;
                f = *(const float2*)(Ab + r0 * F + c0); a[m][k][0] = cvt2(f.x * CEXP, f.y * CEXP);
                f = *(const float2*)(Ab + r1 * F + c0); a[m][k][1] = cvt2(f.x * CEXP, f.y * CEXP);
                f = *(const float2*)(Ab + r0 * F + c1); a[m][k][2] = cvt2(f.x * CEXP, f.y * CEXP);
                f = *(const float2*)(Ab + r1 * F + c1); a[m][k][3] = cvt2(f.x * CEXP, f.y * CEXP);
            }
    }

    // fp32 staging: 64 rows x 512B; each thread 4 x 16B
    const int srow = tid >> 3;
    const int sseg = (tid & 7) * 64;
    auto stage = [&](int buf, int qg) {
        const char* src = (const char*)(queue + (size_t)qg * TN * F) + srow * 512 + sseg;
        uint32_t dst = sb + buf * F32_BUF + srow * 512 + sseg;
#pragma unroll
        for (int j = 0; j < 4; j++) cp16(dst + j * 16, src + j * 16);
    };

    // convert one quarter (512 float4) of fp32 buf -> padded bf16 tile
    auto convert_q = [&](int buf, int quarter) {
        int idx = quarter * 512 + tid;           // 0..2047 over full chunk
        int row = idx >> 5, c4 = idx & 31;
        float4 v4 = *((const float4*)(smem + buf * F32_BUF) + idx);
        uint2 o; o.x = cvt2(v4.x, v4.y); o.y = cvt2(v4.z, v4.w);
        *reinterpret_cast<uint2*>(smem + 2 * F32_BUF + buf * BF_BUF + row * SSTR + c4 * 8) = o;
    };

    const int nch = (QG - slot + SLOTS - 1) / SLOTS;   // 6 or 7

    float s00 = 0.f, s01 = 0.f, s10 = 0.f, s11 = 0.f;

    stage(0, slot); cp_commit();
    stage(1, slot + SLOTS); cp_commit();
    cp_wait1();                    // stage(0) done
#pragma unroll
    for (int q = 0; q < 4; q++) convert_q(0, q);
    __syncthreads();

    int qg = slot;
#pragma unroll 1
    for (int c = 0; c < nch; c++, qg += SLOTS) {
        if (c + 2 < nch) stage(c & 1, qg + 2 * SLOTS);   // fp32 buf (c+2)&1 == c&1
        cp_commit();                                      // keep group count uniform

        const uint32_t lbase = bf_b + (c & 1) * BF_BUF + (lane & 7) * SSTR + (lane >> 3) * 16;
        const bool has_next = (c + 1 < nch);

#pragma unroll
        for (int n8 = 0; n8 < 8; n8++) {
            if (n8 == 4) cp_wait1();                      // stage(c+1) landed
            if (n8 >= 4 && has_next) convert_q((c + 1) & 1, n8 - 4);

            const uint32_t nb = lbase + n8 * 8 * SSTR;
            float x0[4] = {0,0,0,0}, x1[4] = {0,0,0,0};
            float y0[4] = {0,0,0,0}, y1[4] = {0,0,0,0};
#pragma unroll
            for (int kp = 0; kp < 4; kp++) {
                uint32_t bq[4];
                ldsm_x4(bq, nb + kp * 64);
                float* dx = (kp < 2) ? x0 : x1;
                float* dy = (kp < 2) ? y0 : y1;
                mma16816(dx, a[0][2 * kp],     bq[0], bq[1]);
                mma16816(dx, a[0][2 * kp + 1], bq[2], bq[3]);
                mma16816(dy, a[1][2 * kp],     bq[0], bq[1]);
                mma16816(dy, a[1][2 * kp + 1], bq[2], bq[3]);
            }
            s00 += ex2f(x0[0] + x1[0]) + ex2f(x0[1] + x1[1]);
            s01 += ex2f(x0[2] + x1[2]) + ex2f(x0[3] + x1[3]);
            s10 += ex2f(y0[0] + y1[0]) + ex2f(y0[1] + y1[1]);
            s11 += ex2f(y0[2] + y1[2]) + ex2f(y0[3] + y1[3]);
        }
        __syncthreads();   // tile (c+1) visible to all; mma(c) done before its buffers reused
    }

    // ---- quad reduce over tg, transposed deterministic store ----
    s00 += __shfl_xor_sync(0xFFFFFFFFu, s00, 1); s00 += __shfl_xor_sync(0xFFFFFFFFu, s00, 2);
    s01 += __shfl_xor_sync(0xFFFFFFFFu, s01, 1); s01 += __shfl_xor_sync(0xFFFFFFFFu, s01, 2);
    s10 += __shfl_xor_sync(0xFFFFFFFFu, s10, 1); s10 += __shfl_xor_sync(0xFFFFFFFFu, s10, 2);
    s11 += __shfl_xor_sync(0xFFFFFFFFu, s11, 1); s11 += __shfl_xor_sync(0xFFFFFFFFu, s11, 2);
    if (tg == 0) {
        int rb = w * 32;
        g_sq[(size_t)(rb + g)      * SLOTS + slot] = s00;
        g_sq[(size_t)(rb + g + 8)  * SLOTS + slot] = s01;
        g_sq[(size_t)(rb + g + 16) * SLOTS + slot] = s10;
        g_sq[(size_t)(rb + g + 24) * SLOTS + slot] = s11;
    }
}

// ================= kernel 2: per-row pos + slot reduction (64 CTAs, warp/row) =================
__global__ void __launch_bounds__(256) reduce_kernel(const float* __restrict__ V,
                                                     const float* __restrict__ L) {
    const int w    = threadIdx.x >> 5;
    const int lane = threadIdx.x & 31;
    const int row  = blockIdx.x * 8 + w;      // 64 CTAs x 8 warps = 512 rows

    // pos: lane handles 4 consecutive floats
    float4 av = ((const float4*)(V + (size_t)row * F))[lane];
    float4 lv = ((const float4*)(L + (size_t)(row & (B - 1)) * F))[lane];
    float p = av.x * lv.x + av.y * lv.y + av.z * lv.z + av.w * lv.w;
#pragma unroll
    for (int o = 16; o > 0; o >>= 1) p += __shfl_xor_sync(0xFFFFFFFFu, p, o);

    // S_q: lanes split 148 slots (coalesced: [row][slot])
    const float* sr = g_sq + (size_t)row * SLOTS;
    float sq = 0.f;
#pragma unroll
    for (int i = lane; i < SLOTS; i += 32) sq += sr[i];
#pragma unroll
    for (int o = 16; o > 0; o >>= 1) sq += __shfl_xor_sync(0xFFFFFFFFu, sq, o);

    if (lane == 0) {
        g_pos[row]   = p * INV_T;
        g_sqrow[row] = sq;
    }
}

// ================= kernel 3: final loss (tiny) =================
__global__ void final_kernel(float* __restrict__ out) {
    __shared__ float sh[R];
    int t = threadIdx.x;          // 512
    float pos = g_pos[t];
    float sq  = g_sqrow[t];
    sh[t] = ex2f(pos * LOG2E);
    __syncthreads();
    for (int off = 128; off > 0; off >>= 1) {
        if ((t & 255) < off) sh[t] += sh[t + off];
        __syncthreads();
    }
    float spos = sh[(t >> 8) << 8];
    __syncthreads();
    sh[t] = pos - logf(spos + sq);
    __syncthreads();
    for (int off = 256; off > 0; off >>= 1) {
        if (t < off) sh[t] += sh[t + off];
        __syncthreads();
    }
    if (t == 0) out[0] = -sh[0] / (float)B;
}

// ================= launch =================
extern "C" void kernel_launch(void* const* d_in, const int* in_sizes, int n_in,
                              void* d_out, int out_size) {
    (void)in_sizes; (void)n_in; (void)out_size;
    const float* V     = (const float*)d_in[0];
    const float* L     = (const float*)d_in[1];
    const float* queue = (const float*)d_in[2];
    float* out = (float*)d_out;

    cudaFuncSetAttribute(gemm_exp_kernel, cudaFuncAttributeMaxDynamicSharedMemorySize, SMEM_BYTES);

    gemm_exp_kernel<<<SLOTS, 512, SMEM_BYTES>>>(V, queue);
    reduce_kernel<<<64, 256>>>(V, L);
    final_kernel<<<1, 512>>>(out);
}